// round 14
// baseline (speedup 1.0000x reference)
#include <cuda_runtime.h>
#include <cuda_bf16.h>
#include <cstdint>

// LSTM char-RNN — R14: split-bf16 mma.sync (HMMA) rewrite. No tcgen05 (the
// harness builds non-arch-specific PTX; tcgen05 requires sm_103a target).
//
// z_t = x_proj + h_{t-1} @ R via mma.sync.m16n8k16 bf16, fp32 accum, 3 passes
// (hi*hi + hi*lo + lo*hi). Grid 128 CTAs = 16 M-blocks (64 batch rows) x
// 8 N-slices (128 z-cols, n = u_local*4 + gate), cluster(8) = one M-block.
//  - R slice bf16 hi+lo weight-stationary in SMEM ([n][k], padded rows).
//  - h bf16 hi/lo in global, double-buffered; exchange via cluster barrier
//    (arrive=release, wait=acquire) + __ldcg (L1 may be stale).
//  - Fragments via plain LDS at documented m16n8k16 lane mappings.

#define SEQLEN 256
#define UNITSN 256
#define NCHARS 128
#define BATCHN 1024
#define MB     64         // batch rows per M-block
#define NMB    16         // M-blocks
#define NSL    8          // N-slices (cluster size)
#define NTHR   256
#define KP     264        // padded k-stride (elems) for A and B smem rows

// SMEM offsets (bytes)
#define SM_AHI 0
#define SM_ALO 33792      // 64*264*2
#define SM_BHI 67584
#define SM_BLO 135168     // + 128*264*2
#define SM_IDX 202752     // 256*64 bytes
#define SM_HH  219136     // 64*32*2
#define SM_HL  223232
#define SM_TOT 227328

__device__ float         Wxb_g[NCHARS * 1024];              // x-proj + bias, permuted
__device__ __nv_bfloat16 h_hi_g[2 * NMB * MB * UNITSN];     // [buf][mblk][row][unit]
__device__ __nv_bfloat16 h_lo_g[2 * NMB * MB * UNITSN];

__device__ __forceinline__ void mma_bf16(float* c, const uint32_t* a, const uint32_t* b) {
    asm("mma.sync.aligned.m16n8k16.row.col.f32.bf16.bf16.f32 "
        "{%0,%1,%2,%3}, {%4,%5,%6,%7}, {%8,%9}, {%0,%1,%2,%3};"
        : "+f"(c[0]), "+f"(c[1]), "+f"(c[2]), "+f"(c[3])
        : "r"(a[0]), "r"(a[1]), "r"(a[2]), "r"(a[3]), "r"(b[0]), "r"(b[1]));
}

#define CLUSTER_SYNC() do { \
    asm volatile("barrier.cluster.arrive.aligned;" ::: "memory"); \
    asm volatile("barrier.cluster.wait.aligned;"   ::: "memory"); } while (0)

// exp-based activations (~1e-6 rel err; tanh.approx would not survive)
__device__ __forceinline__ float fast_sigmoid(float x) {
    return __fdividef(1.0f, 1.0f + __expf(-x));
}
__device__ __forceinline__ float fast_tanh(float x) {
    float e = __expf(2.0f * x);
    return 1.0f - __fdividef(2.0f, e + 1.0f);
}

// ---------------- pre-pass ----------------
__global__ void prepass_kernel(const float* __restrict__ Wx,
                               const float* __restrict__ bias)
{
    const int c = blockIdx.x;          // 0..127
    const int tid = threadIdx.x;
    // Wxb[c][n_global], n_global = j*128 + u_l*4 + g  ->  col = g*256 + 32j + u_l
    for (int n = tid; n < 1024; n += NTHR) {
        int jj = n >> 7, r = n & 127, u_l = r >> 2, g = r & 3;
        int col = g * UNITSN + 32 * jj + u_l;
        Wxb_g[c * 1024 + n] = Wx[c * 1024 + col] + bias[col];
    }
    // zero h buffer 0 (hi+lo)
    uint32_t* zh = (uint32_t*)h_hi_g;
    uint32_t* zl = (uint32_t*)h_lo_g;
    const int nu32 = NMB * MB * UNITSN / 2;    // buf0 only
    for (int e = blockIdx.x * NTHR + tid; e < nu32; e += gridDim.x * NTHR) {
        zh[e] = 0u; zl[e] = 0u;
    }
}

// ---------------- main persistent LSTM ----------------
__global__ void __launch_bounds__(NTHR, 1) __cluster_dims__(NSL, 1, 1)
lstm_mma_kernel(const int* __restrict__ inp, const float* __restrict__ R)
{
    extern __shared__ __align__(16) char smem[];
    __nv_bfloat16* Ah = (__nv_bfloat16*)(smem + SM_AHI);
    __nv_bfloat16* Al = (__nv_bfloat16*)(smem + SM_ALO);
    __nv_bfloat16* Bh = (__nv_bfloat16*)(smem + SM_BHI);
    __nv_bfloat16* Bl = (__nv_bfloat16*)(smem + SM_BLO);
    unsigned char* idxs = (unsigned char*)(smem + SM_IDX);
    __nv_bfloat16* Hh = (__nv_bfloat16*)(smem + SM_HH);
    __nv_bfloat16* Hl = (__nv_bfloat16*)(smem + SM_HL);

    const int tid  = threadIdx.x;
    const int lane = tid & 31;
    const int wid  = tid >> 5;
    const int j    = blockIdx.x & 7;        // N-slice
    const int ib   = blockIdx.x >> 3;       // M-block
    const int wm   = wid >> 2;              // warp rows [32wm, 32wm+32)
    const int wn   = wid & 3;               // warp cols [32wn, 32wn+32)

    // ---- one-time: R slice -> SMEM bf16 hi/lo, B[n][k] layout ----
    for (int e = tid; e < 128 * 256; e += NTHR) {
        int n = e & 127, k = e >> 7;
        int col = (n & 3) * UNITSN + 32 * j + (n >> 2);
        float v = R[k * 1024 + col];
        __nv_bfloat16 hi = __float2bfloat16(v);
        __nv_bfloat16 lo = __float2bfloat16(v - __bfloat162float(hi));
        Bh[n * KP + k] = hi;
        Bl[n * KP + k] = lo;
    }
    // ---- one-time: all step indices ----
    for (int e = tid; e < SEQLEN * MB; e += NTHR) {
        int row = e & 63, t = e >> 6;
        idxs[t * MB + row] = (unsigned char)inp[(ib * MB + row) * SEQLEN + t];
    }
    __syncthreads();

    float c_st[2][4];
#pragma unroll
    for (int a = 0; a < 2; ++a)
#pragma unroll
        for (int b = 0; b < 4; ++b) c_st[a][b] = 0.0f;

    for (int t = 0; t < SEQLEN; ++t) {
        CLUSTER_SYNC();            // release(h writes t-1) / acquire

        const int rb = t & 1, wb = rb ^ 1;
        // ---- load h M-block (bf16 hi/lo) -> A smem ----
        {
            const uint4* gh = (const uint4*)(h_hi_g + (rb * NMB + ib) * MB * UNITSN);
            const uint4* gl = (const uint4*)(h_lo_g + (rb * NMB + ib) * MB * UNITSN);
#pragma unroll
            for (int it = 0; it < 8; ++it) {
                int q = tid + it * NTHR;            // 0..2047
                int row = q >> 5, cq = q & 31;      // 32 x uint4 per row
                uint4 vh = __ldcg(gh + q);
                uint4 vl = __ldcg(gl + q);
                *(uint4*)&Ah[row * KP + cq * 8] = vh;
                *(uint4*)&Al[row * KP + cq * 8] = vl;
            }
        }
        __syncthreads();

        // ---- MMA mainloop ----
        float acc[2][4][4];
#pragma unroll
        for (int a = 0; a < 2; ++a)
#pragma unroll
            for (int b = 0; b < 4; ++b)
#pragma unroll
                for (int q = 0; q < 4; ++q) acc[a][b][q] = 0.0f;

#pragma unroll 2
        for (int kt = 0; kt < 16; ++kt) {
            const int k0 = kt * 16 + (lane & 3) * 2;
            uint32_t Af[2][4], Afl[2][4];
#pragma unroll
            for (int mt = 0; mt < 2; ++mt) {
                int ra = 32 * wm + 16 * mt + (lane >> 2);
                Af[mt][0]  = *(const uint32_t*)&Ah[ra * KP + k0];
                Af[mt][1]  = *(const uint32_t*)&Ah[(ra + 8) * KP + k0];
                Af[mt][2]  = *(const uint32_t*)&Ah[ra * KP + k0 + 8];
                Af[mt][3]  = *(const uint32_t*)&Ah[(ra + 8) * KP + k0 + 8];
                Afl[mt][0] = *(const uint32_t*)&Al[ra * KP + k0];
                Afl[mt][1] = *(const uint32_t*)&Al[(ra + 8) * KP + k0];
                Afl[mt][2] = *(const uint32_t*)&Al[ra * KP + k0 + 8];
                Afl[mt][3] = *(const uint32_t*)&Al[(ra + 8) * KP + k0 + 8];
            }
            uint32_t Bf[4][2], Bfl[4][2];
#pragma unroll
            for (int nt = 0; nt < 4; ++nt) {
                int nr = 32 * wn + 8 * nt + (lane >> 2);
                Bf[nt][0]  = *(const uint32_t*)&Bh[nr * KP + k0];
                Bf[nt][1]  = *(const uint32_t*)&Bh[nr * KP + k0 + 8];
                Bfl[nt][0] = *(const uint32_t*)&Bl[nr * KP + k0];
                Bfl[nt][1] = *(const uint32_t*)&Bl[nr * KP + k0 + 8];
            }
#pragma unroll
            for (int mt = 0; mt < 2; ++mt)
#pragma unroll
                for (int nt = 0; nt < 4; ++nt) {
                    mma_bf16(acc[mt][nt], Af[mt],  Bf[nt]);   // hi*hi
                    mma_bf16(acc[mt][nt], Af[mt],  Bfl[nt]);  // hi*lo
                    mma_bf16(acc[mt][nt], Afl[mt], Bf[nt]);   // lo*hi
                }
        }

        // ---- epilogue: lane pair (even: i,f / odd: g,o) exchange ----
        const int par = lane & 1;
        const int e2  = (lane >> 1) & 1;
#pragma unroll
        for (int mt = 0; mt < 2; ++mt) {
#pragma unroll
            for (int nt = 0; nt < 4; ++nt) {
                float* a4 = acc[mt][nt];
                float d0 = __shfl_down_sync(0xffffffffu, a4[0], 1);
                float d1 = __shfl_down_sync(0xffffffffu, a4[1], 1);
                float u2 = __shfl_up_sync(0xffffffffu, a4[2], 1);
                float u3 = __shfl_up_sync(0xffffffffu, a4[3], 1);
                float zi = par ? u2 : a4[0];
                float zf = par ? u3 : a4[1];
                float zg = par ? a4[2] : d0;
                float zo = par ? a4[3] : d1;
                int row = 32 * wm + 16 * mt + (lane >> 2) + 8 * par;
                int u_l = 8 * wn + 2 * nt + e2;
                int ch  = idxs[t * MB + row];
                float4 xq = *(const float4*)&Wxb_g[ch * 1024 + j * 128 + u_l * 4];
                zi += xq.x; zf += xq.y; zg += xq.z; zo += xq.w;
                float ig = fast_sigmoid(zi);
                float fg = fast_sigmoid(zf);
                float gg = fast_tanh(zg);
                float og = fast_sigmoid(zo);
                float c  = fg * c_st[mt][nt] + ig * gg;
                c_st[mt][nt] = c;
                float h  = og * fast_tanh(c);
                __nv_bfloat16 hh = __float2bfloat16(h);
                __nv_bfloat16 hl = __float2bfloat16(h - __bfloat162float(hh));
                Hh[row * 32 + u_l] = hh;
                Hl[row * 32 + u_l] = hl;
            }
        }
        __syncthreads();

        // ---- coalesced STG of CTA's h chunk [64 rows][32 units] ----
        {
            int row = tid >> 2, qq = tid & 3;      // 4 x uint4 per row
            uint4 vh = *(const uint4*)&Hh[row * 32 + qq * 8];
            uint4 vl = *(const uint4*)&Hl[row * 32 + qq * 8];
            *(uint4*)&h_hi_g[((wb * NMB + ib) * MB + row) * UNITSN + j * 32 + qq * 8] = vh;
            *(uint4*)&h_lo_g[((wb * NMB + ib) * MB + row) * UNITSN + j * 32 + qq * 8] = vl;
        }
        // next CLUSTER_SYNC releases these stores
    }
}

// ---------------- final dense + softmax ----------------
__global__ void __launch_bounds__(NTHR, 1) dense_softmax_kernel(
    const float* __restrict__ Wd, const float* __restrict__ bd,
    float* __restrict__ out)
{
    __shared__ float h_s[8][UNITSN];
    const int tid = threadIdx.x;
    const int b0 = blockIdx.x * 8;
    for (int e = tid; e < 8 * UNITSN; e += NTHR) {
        int rr = e >> 8, u = e & 255;
        int row = b0 + rr, mb = row >> 6, rl = row & 63;
        int gi = (0 * NMB + mb) * MB * UNITSN + rl * UNITSN + u;   // final h in buf 0
        h_s[rr][u] = __bfloat162float(h_hi_g[gi]) + __bfloat162float(h_lo_g[gi]);
    }
    __syncthreads();
    const int w = tid >> 5, l = tid & 31;
    float4 bb = ((const float4*)bd)[l];
    float a0 = bb.x, a1 = bb.y, a2 = bb.z, a3 = bb.w;
#pragma unroll 4
    for (int u = 0; u < UNITSN; ++u) {
        float hv = h_s[w][u];
        float4 wv = *(const float4*)(Wd + u * NCHARS + 4 * l);
        a0 += hv * wv.x; a1 += hv * wv.y; a2 += hv * wv.z; a3 += hv * wv.w;
    }
    float m = fmaxf(fmaxf(a0, a1), fmaxf(a2, a3));
#pragma unroll
    for (int off = 16; off; off >>= 1)
        m = fmaxf(m, __shfl_xor_sync(0xffffffffu, m, off));
    float e0 = __expf(a0 - m), e1 = __expf(a1 - m);
    float e2 = __expf(a2 - m), e3 = __expf(a3 - m);
    float s = e0 + e1 + e2 + e3;
#pragma unroll
    for (int off = 16; off; off >>= 1)
        s += __shfl_xor_sync(0xffffffffu, s, off);
    float inv = 1.0f / s;
    *(float4*)(out + (b0 + w) * NCHARS + 4 * l) =
        make_float4(e0 * inv, e1 * inv, e2 * inv, e3 * inv);
}

extern "C" void kernel_launch(void* const* d_in, const int* in_sizes, int n_in,
                              void* d_out, int out_size)
{
    const int*   inp  = (const int*)d_in[0];    // [1024, 256]
    const float* Wx   = (const float*)d_in[1];  // [128, 1024]
    const float* R    = (const float*)d_in[2];  // [256, 1024]
    const float* bias = (const float*)d_in[3];  // [1024]
    const float* Wd   = (const float*)d_in[4];  // [256, 128]
    const float* bd   = (const float*)d_in[5];  // [128]
    float*       out  = (float*)d_out;          // [1024, 128]

    cudaFuncSetAttribute(lstm_mma_kernel,
                         cudaFuncAttributeMaxDynamicSharedMemorySize, SM_TOT);
    prepass_kernel<<<NCHARS, NTHR>>>(Wx, bias);
    lstm_mma_kernel<<<NMB * NSL, NTHR, SM_TOT>>>(inp, R);
    dense_softmax_kernel<<<BATCHN / 8, NTHR>>>(Wd, bd, out);
}

// round 15
// speedup vs baseline: 1.1790x; 1.1790x over previous
#include <cuda_runtime.h>
#include <cuda_bf16.h>
#include <cstdint>

// LSTM char-RNN — R15: split-bf16 mma.sync, 512 thr, ldmatrix, prefetch.
//
// z_t = x_proj + h_{t-1} @ R via mma.sync.m16n8k16 bf16 fp32-acc, 3 passes
// (hi*hi + hi*lo + lo*hi). Grid 128 CTAs = 16 M-blocks (64 batch rows) x
// 8 N-slices (128 z-cols, n = u_local*4 + gate), cluster(8) = one M-block.
// R slice bf16 hi+lo weight-stationary in SMEM. h bf16 hi/lo in global,
// double-buffered, exchanged via cluster.sync (+ __ldcg). Fragments via
// ldmatrix.x4 (layout verified by R14's scalar-load pass @ rel_err 1e-7).

#define SEQLEN 256
#define UNITSN 256
#define NCHARS 128
#define BATCHN 1024
#define MB     64
#define NMB    16
#define NSL    8
#define NTHR   512
#define KP     264              // padded k-stride (elems)
#define KPB    (KP * 2)         // row stride bytes = 528

// SMEM offsets (bytes)
#define SM_AHI 0
#define SM_ALO 33792            // 64*528
#define SM_BHI 67584
#define SM_BLO 135168           // +128*528
#define SM_IDX 202752
#define SM_HH  219136           // +256*64
#define SM_HL  223232
#define SM_TOT 227328

__device__ float         Wxb_g[NCHARS * 1024];
__device__ __nv_bfloat16 h_hi_g[2 * NMB * MB * UNITSN];
__device__ __nv_bfloat16 h_lo_g[2 * NMB * MB * UNITSN];

__device__ __forceinline__ void mma_bf16(float* c, const uint32_t* a, const uint32_t* b) {
    asm("mma.sync.aligned.m16n8k16.row.col.f32.bf16.bf16.f32 "
        "{%0,%1,%2,%3}, {%4,%5,%6,%7}, {%8,%9}, {%0,%1,%2,%3};"
        : "+f"(c[0]), "+f"(c[1]), "+f"(c[2]), "+f"(c[3])
        : "r"(a[0]), "r"(a[1]), "r"(a[2]), "r"(a[3]), "r"(b[0]), "r"(b[1]));
}
__device__ __forceinline__ void ldsm_x4(uint32_t* r, uint32_t addr) {
    asm volatile("ldmatrix.sync.aligned.m8n8.x4.shared.b16 {%0,%1,%2,%3}, [%4];"
        : "=r"(r[0]), "=r"(r[1]), "=r"(r[2]), "=r"(r[3]) : "r"(addr));
}
__device__ __forceinline__ uint32_t smem_u32(const void* p) {
    uint32_t a;
    asm("{ .reg .u64 t; cvta.to.shared.u64 t, %1; cvt.u32.u64 %0, t; }"
        : "=r"(a) : "l"(p));
    return a;
}
#define CLUSTER_SYNC() do { \
    asm volatile("barrier.cluster.arrive.aligned;" ::: "memory"); \
    asm volatile("barrier.cluster.wait.aligned;"   ::: "memory"); } while (0)

__device__ __forceinline__ float fast_sigmoid(float x) {
    return __fdividef(1.0f, 1.0f + __expf(-x));
}
__device__ __forceinline__ float fast_tanh(float x) {
    float e = __expf(2.0f * x);
    return 1.0f - __fdividef(2.0f, e + 1.0f);
}

// ---------------- pre-pass ----------------
__global__ void prepass_kernel(const float* __restrict__ Wx,
                               const float* __restrict__ bias)
{
    const int c = blockIdx.x;
    const int tid = threadIdx.x;
    for (int n = tid; n < 1024; n += 256) {
        int jj = n >> 7, r = n & 127, u_l = r >> 2, g = r & 3;
        int col = g * UNITSN + 32 * jj + u_l;
        Wxb_g[c * 1024 + n] = Wx[c * 1024 + col] + bias[col];
    }
    uint32_t* zh = (uint32_t*)h_hi_g;
    uint32_t* zl = (uint32_t*)h_lo_g;
    const int nu32 = NMB * MB * UNITSN / 2;
    for (int e = blockIdx.x * 256 + tid; e < nu32; e += gridDim.x * 256) {
        zh[e] = 0u; zl[e] = 0u;
    }
}

// ---------------- main persistent LSTM ----------------
__global__ void __launch_bounds__(NTHR, 1) __cluster_dims__(NSL, 1, 1)
lstm_mma_kernel(const int* __restrict__ inp, const float* __restrict__ R)
{
    extern __shared__ __align__(16) char smem[];
    __nv_bfloat16* Ah = (__nv_bfloat16*)(smem + SM_AHI);
    __nv_bfloat16* Al = (__nv_bfloat16*)(smem + SM_ALO);
    __nv_bfloat16* Bh = (__nv_bfloat16*)(smem + SM_BHI);
    __nv_bfloat16* Bl = (__nv_bfloat16*)(smem + SM_BLO);
    unsigned char* idxs = (unsigned char*)(smem + SM_IDX);
    __nv_bfloat16* Hh = (__nv_bfloat16*)(smem + SM_HH);
    __nv_bfloat16* Hl = (__nv_bfloat16*)(smem + SM_HL);

    const int tid  = threadIdx.x;
    const int lane = tid & 31;
    const int wid  = tid >> 5;
    const int j    = blockIdx.x & 7;
    const int ib   = blockIdx.x >> 3;
    const int wm   = wid >> 2;            // rows [16wm, 16wm+16)
    const int wn   = wid & 3;             // cols [32wn, 32wn+32)

    // ---- one-time: R slice -> SMEM bf16 hi/lo ([n][k], padded) ----
    for (int e = tid; e < 128 * 256; e += NTHR) {
        int n = e & 127, k = e >> 7;
        int col = (n & 3) * UNITSN + 32 * j + (n >> 2);
        float v = R[k * 1024 + col];
        __nv_bfloat16 hi = __float2bfloat16(v);
        __nv_bfloat16 lo = __float2bfloat16(v - __bfloat162float(hi));
        Bh[n * KP + k] = hi;
        Bl[n * KP + k] = lo;
    }
    for (int e = tid; e < SEQLEN * MB; e += NTHR) {
        int row = e & 63, t = e >> 6;
        idxs[t * MB + row] = (unsigned char)inp[(ib * MB + row) * SEQLEN + t];
    }
    __syncthreads();

    // ---- precompute ldmatrix lane addresses (step-invariant; +32 B/kt) ----
    // A x4 (m16k16): tiles {m0k0, m8k0, m0k8, m8k8}; lane L supplies row of
    // tile L>>3: row = 16wm + (L&7) + ((L>>3)&1)*8, k-halve byte off (L>>4)*16.
    const uint32_t smb = smem_u32(smem);
    const uint32_t aA  = smb + SM_AHI
        + (uint32_t)((16 * wm + (lane & 7) + ((lane >> 3) & 1) * 8) * KPB)
        + (uint32_t)((lane >> 4) * 16);
    const uint32_t aAl_ = aA + (SM_ALO - SM_AHI);
    // B x4 covers an nt pair (16 n rows): tiles {n0k0, n0k8, n8k0, n8k8};
    // row = nb + (L&7) + (L>>4)*8, k byte off ((L>>3)&1)*16.
    const uint32_t brow = (uint32_t)((32 * wn + (lane & 7) + (lane >> 4) * 8) * KPB)
                        + (uint32_t)(((lane >> 3) & 1) * 16);
    const uint32_t aB0 = smb + SM_BHI + brow;            // nt 0,1
    const uint32_t aB1 = aB0 + 16 * KPB;                 // nt 2,3
    const uint32_t aBl0 = aB0 + (SM_BLO - SM_BHI);
    const uint32_t aBl1 = aB1 + (SM_BLO - SM_BHI);

    const int par = lane & 1;             // 0: i,f owner  1: g,o owner
    const int e2  = (lane >> 1) & 1;
    const int rowE = 16 * wm + (lane >> 2) + 8 * par;    // epilogue row

    float c_st[4] = {0.f, 0.f, 0.f, 0.f};

    for (int t = 0; t < SEQLEN; ++t) {
        CLUSTER_SYNC();            // release h(t-1) / acquire peers'

        const int rb = t & 1, wb = rb ^ 1;
        // ---- load h M-block (hi/lo) -> A smem ----
        {
            const uint4* gh = (const uint4*)(h_hi_g + (rb * NMB + ib) * MB * UNITSN);
            const uint4* gl = (const uint4*)(h_lo_g + (rb * NMB + ib) * MB * UNITSN);
#pragma unroll
            for (int it = 0; it < 4; ++it) {
                int q = tid + it * NTHR;            // 0..2047
                int row = q >> 5, cq = q & 31;
                uint4 vh = __ldcg(gh + q);
                uint4 vl = __ldcg(gl + q);
                *(uint4*)&Ah[row * KP + cq * 8] = vh;
                *(uint4*)&Al[row * KP + cq * 8] = vl;
            }
        }
        __syncthreads();

        // ---- Wxb prefetch (overlaps MMA; consumed in epilogue) ----
        const int ch = idxs[t * MB + rowE];
        const float4* wxp = (const float4*)&Wxb_g[ch * 1024 + j * 128];
        float4 xq[4];
#pragma unroll
        for (int nt = 0; nt < 4; ++nt)
            xq[nt] = wxp[8 * wn + 2 * nt + e2];

        // ---- MMA mainloop: 16 kt x (6 LDSM.x4 + 12 HMMA) ----
        float acc[4][4];
#pragma unroll
        for (int nt = 0; nt < 4; ++nt)
#pragma unroll
            for (int q = 0; q < 4; ++q) acc[nt][q] = 0.0f;

#pragma unroll 4
        for (int kt = 0; kt < 16; ++kt) {
            const uint32_t off = (uint32_t)kt * 32;
            uint32_t fAh[4], fAl[4], fB0[4], fB1[4], fL0[4], fL1[4];
            ldsm_x4(fAh, aA + off);
            ldsm_x4(fAl, aAl_ + off);
            ldsm_x4(fB0, aB0 + off);
            ldsm_x4(fB1, aB1 + off);
            ldsm_x4(fL0, aBl0 + off);
            ldsm_x4(fL1, aBl1 + off);
            // hi*hi
            mma_bf16(acc[0], fAh, fB0);     mma_bf16(acc[1], fAh, fB0 + 2);
            mma_bf16(acc[2], fAh, fB1);     mma_bf16(acc[3], fAh, fB1 + 2);
            // hi*lo
            mma_bf16(acc[0], fAh, fL0);     mma_bf16(acc[1], fAh, fL0 + 2);
            mma_bf16(acc[2], fAh, fL1);     mma_bf16(acc[3], fAh, fL1 + 2);
            // lo*hi
            mma_bf16(acc[0], fAl, fB0);     mma_bf16(acc[1], fAl, fB0 + 2);
            mma_bf16(acc[2], fAl, fB1);     mma_bf16(acc[3], fAl, fB1 + 2);
        }

        // ---- epilogue: lane-pair exchange, gates, h hi/lo ----
#pragma unroll
        for (int nt = 0; nt < 4; ++nt) {
            float* a4 = acc[nt];
            float d0 = __shfl_down_sync(0xffffffffu, a4[0], 1);
            float d1 = __shfl_down_sync(0xffffffffu, a4[1], 1);
            float u2 = __shfl_up_sync(0xffffffffu, a4[2], 1);
            float u3 = __shfl_up_sync(0xffffffffu, a4[3], 1);
            float zi = par ? u2 : a4[0];
            float zf = par ? u3 : a4[1];
            float zg = par ? a4[2] : d0;
            float zo = par ? a4[3] : d1;
            zi += xq[nt].x; zf += xq[nt].y; zg += xq[nt].z; zo += xq[nt].w;
            float ig = fast_sigmoid(zi);
            float fg = fast_sigmoid(zf);
            float gg = fast_tanh(zg);
            float og = fast_sigmoid(zo);
            float c  = fg * c_st[nt] + ig * gg;
            c_st[nt] = c;
            float h  = og * fast_tanh(c);
            __nv_bfloat16 hh = __float2bfloat16(h);
            __nv_bfloat16 hl = __float2bfloat16(h - __bfloat162float(hh));
            int u_l = 8 * wn + 2 * nt + e2;
            Hh[rowE * 32 + u_l] = hh;
            Hl[rowE * 32 + u_l] = hl;
        }
        __syncthreads();

        // ---- coalesced STG of CTA's h chunk [64 rows][32 units] ----
        {
            int half = tid >> 8;               // 0: hi  1: lo
            int q = tid & 255;
            int row = q >> 2, qq = q & 3;
            const __nv_bfloat16* src = half ? Hl : Hh;
            __nv_bfloat16* dst = half ? h_lo_g : h_hi_g;
            uint4 v = *(const uint4*)&src[row * 32 + qq * 8];
            *(uint4*)&dst[((wb * NMB + ib) * MB + row) * UNITSN + j * 32 + qq * 8] = v;
        }
        // next CLUSTER_SYNC releases these stores
    }
}

// ---------------- final dense + softmax ----------------
__global__ void __launch_bounds__(256, 1) dense_softmax_kernel(
    const float* __restrict__ Wd, const float* __restrict__ bd,
    float* __restrict__ out)
{
    __shared__ float h_s[8][UNITSN];
    const int tid = threadIdx.x;
    const int b0 = blockIdx.x * 8;
    for (int e = tid; e < 8 * UNITSN; e += 256) {
        int rr = e >> 8, u = e & 255;
        int row = b0 + rr, mb = row >> 6, rl = row & 63;
        int gi = mb * MB * UNITSN + rl * UNITSN + u;      // final h in buf 0
        h_s[rr][u] = __bfloat162float(h_hi_g[gi]) + __bfloat162float(h_lo_g[gi]);
    }
    __syncthreads();
    const int w = tid >> 5, l = tid & 31;
    float4 bb = ((const float4*)bd)[l];
    float a0 = bb.x, a1 = bb.y, a2 = bb.z, a3 = bb.w;
#pragma unroll 4
    for (int u = 0; u < UNITSN; ++u) {
        float hv = h_s[w][u];
        float4 wv = *(const float4*)(Wd + u * NCHARS + 4 * l);
        a0 += hv * wv.x; a1 += hv * wv.y; a2 += hv * wv.z; a3 += hv * wv.w;
    }
    float m = fmaxf(fmaxf(a0, a1), fmaxf(a2, a3));
#pragma unroll
    for (int off = 16; off; off >>= 1)
        m = fmaxf(m, __shfl_xor_sync(0xffffffffu, m, off));
    float e0 = __expf(a0 - m), e1 = __expf(a1 - m);
    float e2 = __expf(a2 - m), e3 = __expf(a3 - m);
    float s = e0 + e1 + e2 + e3;
#pragma unroll
    for (int off = 16; off; off >>= 1)
        s += __shfl_xor_sync(0xffffffffu, s, off);
    float inv = 1.0f / s;
    *(float4*)(out + (b0 + w) * NCHARS + 4 * l) =
        make_float4(e0 * inv, e1 * inv, e2 * inv, e3 * inv);
}

extern "C" void kernel_launch(void* const* d_in, const int* in_sizes, int n_in,
                              void* d_out, int out_size)
{
    const int*   inp  = (const int*)d_in[0];    // [1024, 256]
    const float* Wx   = (const float*)d_in[1];  // [128, 1024]
    const float* R    = (const float*)d_in[2];  // [256, 1024]
    const float* bias = (const float*)d_in[3];  // [1024]
    const float* Wd   = (const float*)d_in[4];  // [256, 128]
    const float* bd   = (const float*)d_in[5];  // [128]
    float*       out  = (float*)d_out;          // [1024, 128]

    cudaFuncSetAttribute(lstm_mma_kernel,
                         cudaFuncAttributeMaxDynamicSharedMemorySize, SM_TOT);
    prepass_kernel<<<NCHARS, 256>>>(Wx, bias);
    lstm_mma_kernel<<<NMB * NSL, NTHR, SM_TOT>>>(inp, R);
    dense_softmax_kernel<<<BATCHN / 8, 256>>>(Wd, bd, out);
}

// round 16
// speedup vs baseline: 1.4416x; 1.2228x over previous
#include <cuda_runtime.h>
#include <cuda_fp16.h>
#include <cstdint>

// LSTM char-RNN — R16: fp16 2-pass split MMA + fused dense tail.
//
// z_t = x_proj + h_{t-1} @ R via mma.sync.m16n8k16 f16 fp32-acc, TWO passes:
// (h_hi + h_lo) @ fp16(R).  h split in fp16 is near-exact (~2^-23); the only
// error is R quantization (~1.4e-4 RMS) == running reference with fp16
// weights; measured pipeline damping (R14/15: 2^-18 product err -> 1.0e-7
// final) predicts ~5e-6 final rel_err.
//
// Grid 128 CTAs = 16 M-blocks (64 batch rows) x 8 N-slices (128 z-cols,
// n = u_local*4 + gate), cluster(8) = one M-block. R slice fp16 weight-
// stationary in SMEM. h fp16 hi/lo in global, double-buffered, exchanged via
// cluster barrier + __ldcg. Fragments via ldmatrix.x4 (mapping certified by
// R14==R15 rel_err). t=0 skips the MMA (h0 = 0). Dense+softmax fused as tail.

#define SEQLEN 256
#define UNITSN 256
#define NCHARS 128
#define BATCHN 1024
#define MB     64
#define NMB    16
#define NSL    8
#define NTHR   512
#define KP     264              // padded k-stride (elems)
#define KPB    (KP * 2)         // row stride bytes = 528

// SMEM offsets (bytes)
#define SM_AHI 0
#define SM_ALO 33792            // 64*528
#define SM_BH  67584
#define SM_IDX 135168           // + 128*528
#define SM_HH  151552           // + 256*64
#define SM_HL  155648
#define SM_TOT 159744

__device__ float  Wxb_g[NCHARS * 1024];
__device__ __half h_hi_g[2 * NMB * MB * UNITSN];
__device__ __half h_lo_g[2 * NMB * MB * UNITSN];

__device__ __forceinline__ void mma_f16(float* c, const uint32_t* a, const uint32_t* b) {
    asm("mma.sync.aligned.m16n8k16.row.col.f32.f16.f16.f32 "
        "{%0,%1,%2,%3}, {%4,%5,%6,%7}, {%8,%9}, {%0,%1,%2,%3};"
        : "+f"(c[0]), "+f"(c[1]), "+f"(c[2]), "+f"(c[3])
        : "r"(a[0]), "r"(a[1]), "r"(a[2]), "r"(a[3]), "r"(b[0]), "r"(b[1]));
}
__device__ __forceinline__ void ldsm_x4(uint32_t* r, uint32_t addr) {
    asm volatile("ldmatrix.sync.aligned.m8n8.x4.shared.b16 {%0,%1,%2,%3}, [%4];"
        : "=r"(r[0]), "=r"(r[1]), "=r"(r[2]), "=r"(r[3]) : "r"(addr));
}
__device__ __forceinline__ uint32_t smem_u32(const void* p) {
    uint32_t a;
    asm("{ .reg .u64 t; cvta.to.shared.u64 t, %1; cvt.u32.u64 %0, t; }"
        : "=r"(a) : "l"(p));
    return a;
}
#define CLUSTER_SYNC() do { \
    asm volatile("barrier.cluster.arrive.aligned;" ::: "memory"); \
    asm volatile("barrier.cluster.wait.aligned;"   ::: "memory"); } while (0)

__device__ __forceinline__ float fast_sigmoid(float x) {
    return __fdividef(1.0f, 1.0f + __expf(-x));
}
__device__ __forceinline__ float fast_tanh(float x) {
    float e = __expf(2.0f * x);
    return 1.0f - __fdividef(2.0f, e + 1.0f);
}

// ---------------- pre-pass: Wxb = permuted Wx + bias ----------------
__global__ void prepass_kernel(const float* __restrict__ Wx,
                               const float* __restrict__ bias)
{
    const int c = blockIdx.x;
    const int tid = threadIdx.x;
    for (int n = tid; n < 1024; n += 256) {
        int jj = n >> 7, r = n & 127, u_l = r >> 2, g = r & 3;
        int col = g * UNITSN + 32 * jj + u_l;
        Wxb_g[c * 1024 + n] = Wx[c * 1024 + col] + bias[col];
    }
}

// ---------------- main persistent LSTM + dense tail ----------------
__global__ void __launch_bounds__(NTHR, 1) __cluster_dims__(NSL, 1, 1)
lstm_mma_kernel(const int* __restrict__ inp, const float* __restrict__ R,
                const float* __restrict__ Wd, const float* __restrict__ bd,
                float* __restrict__ out)
{
    extern __shared__ __align__(16) char smem[];
    __half* Ah = (__half*)(smem + SM_AHI);
    __half* Al = (__half*)(smem + SM_ALO);
    __half* Bh = (__half*)(smem + SM_BH);
    unsigned char* idxs = (unsigned char*)(smem + SM_IDX);
    __half* Hh = (__half*)(smem + SM_HH);
    __half* Hl = (__half*)(smem + SM_HL);

    const int tid  = threadIdx.x;
    const int lane = tid & 31;
    const int wid  = tid >> 5;
    const int j    = blockIdx.x & 7;
    const int ib   = blockIdx.x >> 3;
    const int wm   = wid >> 2;            // rows [16wm, 16wm+16)
    const int wn   = wid & 3;             // cols [32wn, 32wn+32)

    // ---- one-time: R slice -> SMEM fp16 ([n][k], padded rows) ----
    for (int e = tid; e < 128 * 256; e += NTHR) {
        int n = e & 127, k = e >> 7;
        int col = (n & 3) * UNITSN + 32 * j + (n >> 2);
        Bh[n * KP + k] = __float2half(R[k * 1024 + col]);
    }
    for (int e = tid; e < SEQLEN * MB; e += NTHR) {
        int row = e & 63, t = e >> 6;
        idxs[t * MB + row] = (unsigned char)inp[(ib * MB + row) * SEQLEN + t];
    }
    __syncthreads();

    // ---- ldmatrix lane addresses (step-invariant) — mapping certified R14/15 ----
    const uint32_t smb = smem_u32(smem);
    const uint32_t aA  = smb + SM_AHI
        + (uint32_t)((16 * wm + (lane & 7) + ((lane >> 3) & 1) * 8) * KPB)
        + (uint32_t)((lane >> 4) * 16);
    const uint32_t aAl_ = aA + (SM_ALO - SM_AHI);
    const uint32_t brow = (uint32_t)((32 * wn + (lane & 7) + (lane >> 4) * 8) * KPB)
                        + (uint32_t)(((lane >> 3) & 1) * 16);
    const uint32_t aB0 = smb + SM_BH + brow;             // nt 0,1
    const uint32_t aB1 = aB0 + 16 * KPB;                 // nt 2,3

    const int par = lane & 1;             // 0: i,f owner  1: g,o owner
    const int e2  = (lane >> 1) & 1;
    const int rowE = 16 * wm + (lane >> 2) + 8 * par;

    float c_st[4] = {0.f, 0.f, 0.f, 0.f};

    for (int t = 0; t < SEQLEN; ++t) {
        CLUSTER_SYNC();            // release h(t-1) / acquire peers'

        const int rb = t & 1, wb = rb ^ 1;

        float acc[4][4];
#pragma unroll
        for (int nt = 0; nt < 4; ++nt)
#pragma unroll
            for (int q = 0; q < 4; ++q) acc[nt][q] = 0.0f;

        // ---- Wxb prefetch (overlaps h-load + MMA) ----
        const int ch = idxs[t * MB + rowE];
        const float4* wxp = (const float4*)&Wxb_g[ch * 1024 + j * 128];
        float4 xq[4];
#pragma unroll
        for (int nt = 0; nt < 4; ++nt)
            xq[nt] = wxp[8 * wn + 2 * nt + e2];

        if (t > 0) {
            // ---- load h M-block (hi/lo) -> A smem ----
            const uint4* gh = (const uint4*)(h_hi_g + (rb * NMB + ib) * MB * UNITSN);
            const uint4* gl = (const uint4*)(h_lo_g + (rb * NMB + ib) * MB * UNITSN);
#pragma unroll
            for (int it = 0; it < 4; ++it) {
                int q = tid + it * NTHR;            // 0..2047
                int row = q >> 5, cq = q & 31;
                uint4 vh = __ldcg(gh + q);
                uint4 vl = __ldcg(gl + q);
                *(uint4*)&Ah[row * KP + cq * 8] = vh;
                *(uint4*)&Al[row * KP + cq * 8] = vl;
            }
            __syncthreads();

            // ---- MMA mainloop: 16 kt x (4 LDSM.x4 + 8 HMMA) ----
#pragma unroll 4
            for (int kt = 0; kt < 16; ++kt) {
                const uint32_t off = (uint32_t)kt * 32;
                uint32_t fAh[4], fAl[4], fB0[4], fB1[4];
                ldsm_x4(fAh, aA + off);
                ldsm_x4(fAl, aAl_ + off);
                ldsm_x4(fB0, aB0 + off);
                ldsm_x4(fB1, aB1 + off);
                mma_f16(acc[0], fAh, fB0);     mma_f16(acc[1], fAh, fB0 + 2);
                mma_f16(acc[2], fAh, fB1);     mma_f16(acc[3], fAh, fB1 + 2);
                mma_f16(acc[0], fAl, fB0);     mma_f16(acc[1], fAl, fB0 + 2);
                mma_f16(acc[2], fAl, fB1);     mma_f16(acc[3], fAl, fB1 + 2);
            }
        }

        // ---- epilogue: lane-pair exchange, gates, h hi/lo ----
#pragma unroll
        for (int nt = 0; nt < 4; ++nt) {
            float* a4 = acc[nt];
            float d0 = __shfl_down_sync(0xffffffffu, a4[0], 1);
            float d1 = __shfl_down_sync(0xffffffffu, a4[1], 1);
            float u2 = __shfl_up_sync(0xffffffffu, a4[2], 1);
            float u3 = __shfl_up_sync(0xffffffffu, a4[3], 1);
            float zi = (par ? u2 : a4[0]) + xq[nt].x;
            float zf = (par ? u3 : a4[1]) + xq[nt].y;
            float zg = (par ? a4[2] : d0) + xq[nt].z;
            float zo = (par ? a4[3] : d1) + xq[nt].w;
            float ig = fast_sigmoid(zi);
            float fg = fast_sigmoid(zf);
            float gg = fast_tanh(zg);
            float og = fast_sigmoid(zo);
            float c  = fg * c_st[nt] + ig * gg;
            c_st[nt] = c;
            float h  = og * fast_tanh(c);
            __half hh = __float2half(h);
            __half hl = __float2half(h - __half2float(hh));
            int u_l = 8 * wn + 2 * nt + e2;
            Hh[rowE * 32 + u_l] = hh;
            Hl[rowE * 32 + u_l] = hl;
        }
        __syncthreads();

        // ---- coalesced STG of CTA's h chunk [64 rows][32 units] ----
        {
            int half = tid >> 8;               // 0: hi  1: lo
            int q = tid & 255;
            int row = q >> 2, qq = q & 3;
            const __half* src = half ? Hl : Hh;
            __half* dst = half ? h_lo_g : h_hi_g;
            uint4 v = *(const uint4*)&src[row * 32 + qq * 8];
            *(uint4*)&dst[((wb * NMB + ib) * MB + row) * UNITSN + j * 32 + qq * 8] = v;
        }
        // next CLUSTER_SYNC releases these stores
    }
    CLUSTER_SYNC();    // final h (buf 0) visible within cluster

    // ---- fused dense + softmax: this CTA handles rows ib*64 + j*8 .. +8 ----
    {
        float* h_s = (float*)(smem);           // reuse A region: 8*256 floats
        __syncthreads();
        for (int e = tid; e < 8 * UNITSN; e += NTHR) {
            int rr = e >> 8, u = e & 255;
            int rl = j * 8 + rr;
            int gi = ib * MB * UNITSN + rl * UNITSN + u;   // final h in buf 0
            h_s[rr * UNITSN + u] =
                __half2float(__ldcg(h_hi_g + gi)) + __half2float(__ldcg(h_lo_g + gi));
        }
        __syncthreads();
        const int w = tid >> 5, l = tid & 31;
        if (w < 8) {
            float4 bb = ((const float4*)bd)[l];
            float a0 = bb.x, a1 = bb.y, a2 = bb.z, a3 = bb.w;
#pragma unroll 4
            for (int u = 0; u < UNITSN; ++u) {
                float hv = h_s[w * UNITSN + u];
                float4 wv = *(const float4*)(Wd + u * NCHARS + 4 * l);
                a0 += hv * wv.x; a1 += hv * wv.y; a2 += hv * wv.z; a3 += hv * wv.w;
            }
            float m = fmaxf(fmaxf(a0, a1), fmaxf(a2, a3));
#pragma unroll
            for (int off = 16; off; off >>= 1)
                m = fmaxf(m, __shfl_xor_sync(0xffffffffu, m, off));
            float e0 = __expf(a0 - m), e1 = __expf(a1 - m);
            float e2f = __expf(a2 - m), e3 = __expf(a3 - m);
            float s = e0 + e1 + e2f + e3;
#pragma unroll
            for (int off = 16; off; off >>= 1)
                s += __shfl_xor_sync(0xffffffffu, s, off);
            float inv = 1.0f / s;
            int rowg = ib * MB + j * 8 + w;
            *(float4*)(out + rowg * NCHARS + 4 * l) =
                make_float4(e0 * inv, e1 * inv, e2f * inv, e3 * inv);
        }
    }
}

extern "C" void kernel_launch(void* const* d_in, const int* in_sizes, int n_in,
                              void* d_out, int out_size)
{
    const int*   inp  = (const int*)d_in[0];    // [1024, 256]
    const float* Wx   = (const float*)d_in[1];  // [128, 1024]
    const float* R    = (const float*)d_in[2];  // [256, 1024]
    const float* bias = (const float*)d_in[3];  // [1024]
    const float* Wd   = (const float*)d_in[4];  // [256, 128]
    const float* bd   = (const float*)d_in[5];  // [128]
    float*       out  = (float*)d_out;          // [1024, 128]

    cudaFuncSetAttribute(lstm_mma_kernel,
                         cudaFuncAttributeMaxDynamicSharedMemorySize, SM_TOT);
    prepass_kernel<<<NCHARS, 256>>>(Wx, bias);
    lstm_mma_kernel<<<NMB * NSL, NTHR, SM_TOT>>>(inp, R, Wd, bd, out);
}

// round 17
// speedup vs baseline: 1.8755x; 1.3010x over previous
#include <cuda_runtime.h>
#include <cuda_fp16.h>
#include <cstdint>

// LSTM char-RNN — R17: single-fp16 h (no hi/lo split) + SMEM Wxb slice.
//
// z_t = x_proj + h_{t-1} @ R via mma.sync.m16n8k16 f16 fp32-acc, ONE pass:
// fp16(h) @ fp16(R). Error model calibrated on R16 (R-quant 1.4e-4 ->
// measured 2.98e-6 final): adding h-quant (~4.9e-4/product) predicts ~1e-5
// final rel_err, 100x under the 1e-3 threshold.
//
// Grid 128 CTAs = 16 M-blocks (64 batch rows) x 8 N-slices (128 z-cols,
// n = u_local*4 + gate), cluster(8) = one M-block. R slice fp16 weight-
// stationary in SMEM; Wxb slice ALSO SMEM-resident (cluster.sync flushes L1
// every step, so global Wxb reads would re-fetch from L2 each step).
// h fp16 in global, double-buffered, exchanged via cluster barrier + __ldcg.
// Fragments via ldmatrix.x4 (mapping certified R14/R15). t=0 skips the MMA.
// Dense+softmax fused as tail (each CTA finishes its own 8 rows).

#define SEQLEN 256
#define UNITSN 256
#define NCHARS 128
#define BATCHN 1024
#define MB     64
#define NMB    16
#define NSL    8
#define NTHR   512
#define KP     264              // padded k-stride (elems)
#define KPB    (KP * 2)         // row stride bytes = 528

// SMEM offsets (bytes)
#define SM_A   0
#define SM_B   33792            // + 64*528
#define SM_WX  101376           // + 128*528
#define SM_IDX 166912           // + 128*128*4
#define SM_H   183296           // + 256*64
#define SM_TOT 187392

__device__ float  Wxb_g[NCHARS * 1024];
__device__ __half h_g[2 * NMB * MB * UNITSN];   // [buf][mblk][row][unit]

__device__ __forceinline__ void mma_f16(float* c, const uint32_t* a, const uint32_t* b) {
    asm("mma.sync.aligned.m16n8k16.row.col.f32.f16.f16.f32 "
        "{%0,%1,%2,%3}, {%4,%5,%6,%7}, {%8,%9}, {%0,%1,%2,%3};"
        : "+f"(c[0]), "+f"(c[1]), "+f"(c[2]), "+f"(c[3])
        : "r"(a[0]), "r"(a[1]), "r"(a[2]), "r"(a[3]), "r"(b[0]), "r"(b[1]));
}
__device__ __forceinline__ void ldsm_x4(uint32_t* r, uint32_t addr) {
    asm volatile("ldmatrix.sync.aligned.m8n8.x4.shared.b16 {%0,%1,%2,%3}, [%4];"
        : "=r"(r[0]), "=r"(r[1]), "=r"(r[2]), "=r"(r[3]) : "r"(addr));
}
__device__ __forceinline__ uint32_t smem_u32(const void* p) {
    uint32_t a;
    asm("{ .reg .u64 t; cvta.to.shared.u64 t, %1; cvt.u32.u64 %0, t; }"
        : "=r"(a) : "l"(p));
    return a;
}
#define CLUSTER_SYNC() do { \
    asm volatile("barrier.cluster.arrive.aligned;" ::: "memory"); \
    asm volatile("barrier.cluster.wait.aligned;"   ::: "memory"); } while (0)

__device__ __forceinline__ float fast_sigmoid(float x) {
    return __fdividef(1.0f, 1.0f + __expf(-x));
}
__device__ __forceinline__ float fast_tanh(float x) {
    float e = __expf(2.0f * x);
    return 1.0f - __fdividef(2.0f, e + 1.0f);
}

// ---------------- pre-pass: Wxb = permuted Wx + bias ----------------
__global__ void prepass_kernel(const float* __restrict__ Wx,
                               const float* __restrict__ bias)
{
    const int c = blockIdx.x;
    const int tid = threadIdx.x;
    for (int n = tid; n < 1024; n += 256) {
        int jj = n >> 7, r = n & 127, u_l = r >> 2, g = r & 3;
        int col = g * UNITSN + 32 * jj + u_l;
        Wxb_g[c * 1024 + n] = Wx[c * 1024 + col] + bias[col];
    }
}

// ---------------- main persistent LSTM + dense tail ----------------
__global__ void __launch_bounds__(NTHR, 1) __cluster_dims__(NSL, 1, 1)
lstm_mma_kernel(const int* __restrict__ inp, const float* __restrict__ R,
                const float* __restrict__ Wd, const float* __restrict__ bd,
                float* __restrict__ out)
{
    extern __shared__ __align__(16) char smem[];
    __half* As = (__half*)(smem + SM_A);
    __half* Bs = (__half*)(smem + SM_B);
    float*  Wxs = (float*)(smem + SM_WX);
    unsigned char* idxs = (unsigned char*)(smem + SM_IDX);
    __half* Hs = (__half*)(smem + SM_H);

    const int tid  = threadIdx.x;
    const int lane = tid & 31;
    const int wid  = tid >> 5;
    const int j    = blockIdx.x & 7;
    const int ib   = blockIdx.x >> 3;
    const int wm   = wid >> 2;            // rows [16wm, 16wm+16)
    const int wn   = wid & 3;             // cols [32wn, 32wn+32)

    // ---- one-time: R slice -> SMEM fp16 ([n][k], padded rows) ----
    for (int e = tid; e < 128 * 256; e += NTHR) {
        int n = e & 127, k = e >> 7;
        int col = (n & 3) * UNITSN + 32 * j + (n >> 2);
        Bs[n * KP + k] = __float2half(R[k * 1024 + col]);
    }
    // ---- one-time: Wxb slice [char][128 cols] -> SMEM ----
    for (int e = tid; e < NCHARS * 32; e += NTHR) {   // 4096 float4
        int c = e >> 5, q = e & 31;
        ((float4*)Wxs)[c * 32 + q] =
            *(const float4*)&Wxb_g[c * 1024 + j * 128 + q * 4];
    }
    // ---- one-time: all step indices ----
    for (int e = tid; e < SEQLEN * MB; e += NTHR) {
        int row = e & 63, t = e >> 6;
        idxs[t * MB + row] = (unsigned char)inp[(ib * MB + row) * SEQLEN + t];
    }
    __syncthreads();

    // ---- ldmatrix lane addresses (step-invariant; mapping certified) ----
    const uint32_t smb = smem_u32(smem);
    const uint32_t aA  = smb + SM_A
        + (uint32_t)((16 * wm + (lane & 7) + ((lane >> 3) & 1) * 8) * KPB)
        + (uint32_t)((lane >> 4) * 16);
    const uint32_t brow = (uint32_t)((32 * wn + (lane & 7) + (lane >> 4) * 8) * KPB)
                        + (uint32_t)(((lane >> 3) & 1) * 16);
    const uint32_t aB0 = smb + SM_B + brow;              // nt 0,1
    const uint32_t aB1 = aB0 + 16 * KPB;                 // nt 2,3

    const int par = lane & 1;             // 0: i,f owner  1: g,o owner
    const int e2  = (lane >> 1) & 1;
    const int rowE = 16 * wm + (lane >> 2) + 8 * par;

    float c_st[4] = {0.f, 0.f, 0.f, 0.f};

    for (int t = 0; t < SEQLEN; ++t) {
        CLUSTER_SYNC();            // release h(t-1) / acquire peers'

        const int rb = t & 1, wb = rb ^ 1;

        float acc[4][4];
#pragma unroll
        for (int nt = 0; nt < 4; ++nt)
#pragma unroll
            for (int q = 0; q < 4; ++q) acc[nt][q] = 0.0f;

        // ---- Wxb fetch from SMEM (cheap LDS; L1-flush-immune) ----
        const int ch = idxs[t * MB + rowE];
        float4 xq[4];
#pragma unroll
        for (int nt = 0; nt < 4; ++nt)
            xq[nt] = ((const float4*)Wxs)[ch * 32 + 8 * wn + 2 * nt + e2];

        if (t > 0) {
            // ---- load h M-block -> A smem (32 KB, 2048 uint4 / 4 per thread) ----
            const uint4* gh = (const uint4*)(h_g + (rb * NMB + ib) * MB * UNITSN);
#pragma unroll
            for (int it = 0; it < 4; ++it) {
                int q = tid + it * NTHR;            // 0..2047
                int row = q >> 5, cq = q & 31;
                uint4 vh = __ldcg(gh + q);
                *(uint4*)&As[row * KP + cq * 8] = vh;
            }
            __syncthreads();

            // ---- MMA mainloop: 16 kt x (3 LDSM.x4 + 4 HMMA) ----
#pragma unroll 4
            for (int kt = 0; kt < 16; ++kt) {
                const uint32_t off = (uint32_t)kt * 32;
                uint32_t fA[4], fB0[4], fB1[4];
                ldsm_x4(fA, aA + off);
                ldsm_x4(fB0, aB0 + off);
                ldsm_x4(fB1, aB1 + off);
                mma_f16(acc[0], fA, fB0);     mma_f16(acc[1], fA, fB0 + 2);
                mma_f16(acc[2], fA, fB1);     mma_f16(acc[3], fA, fB1 + 2);
            }
        }

        // ---- epilogue: lane-pair exchange, gates, h fp16 ----
#pragma unroll
        for (int nt = 0; nt < 4; ++nt) {
            float* a4 = acc[nt];
            float d0 = __shfl_down_sync(0xffffffffu, a4[0], 1);
            float d1 = __shfl_down_sync(0xffffffffu, a4[1], 1);
            float u2 = __shfl_up_sync(0xffffffffu, a4[2], 1);
            float u3 = __shfl_up_sync(0xffffffffu, a4[3], 1);
            float zi = (par ? u2 : a4[0]) + xq[nt].x;
            float zf = (par ? u3 : a4[1]) + xq[nt].y;
            float zg = (par ? a4[2] : d0) + xq[nt].z;
            float zo = (par ? a4[3] : d1) + xq[nt].w;
            float ig = fast_sigmoid(zi);
            float fg = fast_sigmoid(zf);
            float gg = fast_tanh(zg);
            float og = fast_sigmoid(zo);
            float c  = fg * c_st[nt] + ig * gg;
            c_st[nt] = c;
            float h  = og * fast_tanh(c);
            int u_l = 8 * wn + 2 * nt + e2;
            Hs[rowE * 32 + u_l] = __float2half(h);
        }
        __syncthreads();

        // ---- coalesced STG of CTA's h chunk [64 rows][32 units] (4 KB) ----
        if (tid < 256) {
            int row = tid >> 2, qq = tid & 3;
            uint4 v = *(const uint4*)&Hs[row * 32 + qq * 8];
            *(uint4*)&h_g[((wb * NMB + ib) * MB + row) * UNITSN + j * 32 + qq * 8] = v;
        }
        // next CLUSTER_SYNC releases these stores
    }
    CLUSTER_SYNC();    // final h (buf 0) visible

    // ---- fused dense + softmax: this CTA handles rows ib*64 + j*8 .. +8 ----
    {
        float* h_s = (float*)(smem);           // reuse A region (8 KB)
        __syncthreads();
        for (int e = tid; e < 8 * UNITSN; e += NTHR) {
            int rr = e >> 8, u = e & 255;
            int rl = j * 8 + rr;
            h_s[rr * UNITSN + u] =
                __half2float(__ldcg(h_g + ib * MB * UNITSN + rl * UNITSN + u));
        }
        __syncthreads();
        const int w = tid >> 5, l = tid & 31;
        if (w < 8) {
            float4 bb = ((const float4*)bd)[l];
            float a0 = bb.x, a1 = bb.y, a2 = bb.z, a3 = bb.w;
#pragma unroll 4
            for (int u = 0; u < UNITSN; ++u) {
                float hv = h_s[w * UNITSN + u];
                float4 wv = *(const float4*)(Wd + u * NCHARS + 4 * l);
                a0 += hv * wv.x; a1 += hv * wv.y; a2 += hv * wv.z; a3 += hv * wv.w;
            }
            float m = fmaxf(fmaxf(a0, a1), fmaxf(a2, a3));
#pragma unroll
            for (int off = 16; off; off >>= 1)
                m = fmaxf(m, __shfl_xor_sync(0xffffffffu, m, off));
            float e0 = __expf(a0 - m), e1 = __expf(a1 - m);
            float e2f = __expf(a2 - m), e3 = __expf(a3 - m);
            float s = e0 + e1 + e2f + e3;
#pragma unroll
            for (int off = 16; off; off >>= 1)
                s += __shfl_xor_sync(0xffffffffu, s, off);
            float inv = 1.0f / s;
            int rowg = ib * MB + j * 8 + w;
            *(float4*)(out + rowg * NCHARS + 4 * l) =
                make_float4(e0 * inv, e1 * inv, e2f * inv, e3 * inv);
        }
    }
}

extern "C" void kernel_launch(void* const* d_in, const int* in_sizes, int n_in,
                              void* d_out, int out_size)
{
    const int*   inp  = (const int*)d_in[0];    // [1024, 256]
    const float* Wx   = (const float*)d_in[1];  // [128, 1024]
    const float* R    = (const float*)d_in[2];  // [256, 1024]
    const float* bias = (const float*)d_in[3];  // [1024]
    const float* Wd   = (const float*)d_in[4];  // [256, 128]
    const float* bd   = (const float*)d_in[5];  // [128]
    float*       out  = (float*)d_out;          // [1024, 128]

    cudaFuncSetAttribute(lstm_mma_kernel,
                         cudaFuncAttributeMaxDynamicSharedMemorySize, SM_TOT);
    prepass_kernel<<<NCHARS, 256>>>(Wx, bias);
    lstm_mma_kernel<<<NMB * NSL, NTHR, SM_TOT>>>(inp, R, Wd, bd, out);
}